// round 3
// baseline (speedup 1.0000x reference)
#include <cuda_runtime.h>
#include <math.h>

// ---------------- problem constants ----------------
#define Bn    32
#define Cn    384
#define Hn    56
#define Wn    56
#define WSn   7
#define SSn   3
#define NHn   12
#define Nt    49          // tokens per window
#define HDn   32
#define Sn    (Hn*Wn)     // 3136
#define Mrows (Bn*Sn)     // 100352
#define HIDn  1536
#define SCALE 0.17677669529663688f  // 1/sqrt(32)

// ---------------- scratch (device globals; no allocation) ----------------
__device__ float g_xp [(size_t)Mrows*Cn];     // x in BHWC
__device__ float g_xw [(size_t)Mrows*Cn];     // windowed + LN1
__device__ float g_qkv[(size_t)Mrows*3*Cn];
__device__ float g_ao [(size_t)Mrows*Cn];     // attn out (also reused as final BHWC result)
__device__ float g_y  [(size_t)Mrows*Cn];     // residual stream (BHWC)
__device__ float g_xn [(size_t)Mrows*Cn];     // LN2 out
__device__ float g_hid[(size_t)Mrows*HIDn];

// ---------------- batched 32x32 tile transpose  (B matrices R x Cc -> Cc x R) ----
__global__ void transpose_k(const float* __restrict__ in, float* __restrict__ out,
                            int R, int Cc)
{
    __shared__ float tile[32][33];
    int b  = blockIdx.z;
    int c0 = blockIdx.x * 32;
    int r0 = blockIdx.y * 32;
    const float* ib = in  + (size_t)b * R * Cc;
    float*       ob = out + (size_t)b * R * Cc;
    #pragma unroll
    for (int dy = threadIdx.y; dy < 32; dy += 8)
        tile[dy][threadIdx.x] = ib[(size_t)(r0 + dy) * Cc + c0 + threadIdx.x];
    __syncthreads();
    #pragma unroll
    for (int dy = threadIdx.y; dy < 32; dy += 8)
        ob[(size_t)(c0 + dy) * R + r0 + threadIdx.x] = tile[threadIdx.x][dy];
}

// ---------------- LayerNorm (optionally gathering through shift+window map) ----
template<bool GATHER>
__global__ void ln_kernel(const float* __restrict__ in, const float* __restrict__ gamma,
                          const float* __restrict__ beta, float* __restrict__ out)
{
    int tkn = blockIdx.x;
    const float* src;
    if (GATHER) {
        int wl = tkn / Nt, n = tkn % Nt;
        int b = wl >> 6, wi = wl & 63;
        int wh = wi >> 3, ww = wi & 7;
        int i = n / 7, j = n % 7;
        int h = wh * 7 + i + SSn; if (h >= Hn) h -= Hn;
        int w = ww * 7 + j + SSn; if (w >= Wn) w -= Wn;
        src = in + ((size_t)b * Sn + h * Wn + w) * Cn;
    } else {
        src = in + (size_t)tkn * Cn;
    }
    int t = threadIdx.x;
    float v0 = src[t], v1 = src[t + 128], v2 = src[t + 256];
    float s  = v0 + v1 + v2;
    float sq = v0 * v0 + v1 * v1 + v2 * v2;
    #pragma unroll
    for (int off = 16; off; off >>= 1) {
        s  += __shfl_xor_sync(0xffffffffu, s,  off);
        sq += __shfl_xor_sync(0xffffffffu, sq, off);
    }
    __shared__ float ws[4], wq[4];
    if ((t & 31) == 0) { ws[t >> 5] = s; wq[t >> 5] = sq; }
    __syncthreads();
    s  = ws[0] + ws[1] + ws[2] + ws[3];
    sq = wq[0] + wq[1] + wq[2] + wq[3];
    float mean = s * (1.0f / Cn);
    float var  = sq * (1.0f / Cn) - mean * mean;
    float rstd = rsqrtf(var + 1e-5f);
    float* dst = out + (size_t)tkn * Cn;
    dst[t]       = (v0 - mean) * rstd * gamma[t]       + beta[t];
    dst[t + 128] = (v1 - mean) * rstd * gamma[t + 128] + beta[t + 128];
    dst[t + 256] = (v2 - mean) * rstd * gamma[t + 256] + beta[t + 256];
}

// ---------------- fused windowed attention: scores + bias + mask + softmax + @V ----
__global__ void attn_kernel(const float* __restrict__ qkv,
                            const float* __restrict__ rpb,
                            float* __restrict__ out)
{
    int blk = blockIdx.x;                 // w_lin * 12 + head
    int wl  = blk / NHn;
    int hh  = blk % NHn;
    int wi  = wl & 63;
    int wh  = wi >> 3, ww = wi & 7;

    __shared__ float qs[Nt][33], ks[Nt][33], vs[Nt][33];
    __shared__ float as_[Nt][50];

    int t = threadIdx.x;
    const float* base = qkv + (size_t)wl * Nt * (3 * Cn) + hh * HDn;
    for (int e = t; e < Nt * HDn; e += 128) {
        int n = e >> 5, d = e & 31;
        const float* row = base + (size_t)n * (3 * Cn);
        qs[n][d] = row[d] * SCALE;
        ks[n][d] = row[Cn + d];
        vs[n][d] = row[2 * Cn + d];
    }
    __syncthreads();

    for (int e = t; e < Nt * Nt; e += 128) {
        int n = e / Nt, m = e % Nt;
        float s = 0.0f;
        #pragma unroll
        for (int d = 0; d < HDn; d++) s = fmaf(qs[n][d], ks[m][d], s);
        int i1 = n / 7, j1 = n % 7, i2 = m / 7, j2 = m % 7;
        s += rpb[((i1 - i2 + 6) * 13 + (j1 - j2 + 6)) * NHn + hh];
        int h1 = wh * 7 + i1, w1 = ww * 7 + j1;
        int h2 = wh * 7 + i2, w2 = ww * 7 + j2;
        int r1 = (h1 < 49 ? 0 : (h1 < 53 ? 1 : 2)) * 3 + (w1 < 49 ? 0 : (w1 < 53 ? 1 : 2));
        int r2 = (h2 < 49 ? 0 : (h2 < 53 ? 1 : 2)) * 3 + (w2 < 49 ? 0 : (w2 < 53 ? 1 : 2));
        if (r1 != r2) s -= 100.0f;
        as_[n][m] = s;
    }
    __syncthreads();

    if (t < Nt) {
        float mx = -1e30f;
        #pragma unroll
        for (int m = 0; m < Nt; m++) mx = fmaxf(mx, as_[t][m]);
        float sm = 0.0f;
        #pragma unroll
        for (int m = 0; m < Nt; m++) { float e2 = expf(as_[t][m] - mx); as_[t][m] = e2; sm += e2; }
        float inv = 1.0f / sm;
        #pragma unroll
        for (int m = 0; m < Nt; m++) as_[t][m] *= inv;
    }
    __syncthreads();

    float* ob = out + (size_t)wl * Nt * Cn + hh * HDn;
    for (int e = t; e < Nt * HDn; e += 128) {
        int n = e >> 5, d = e & 31;
        float s = 0.0f;
        #pragma unroll
        for (int m = 0; m < Nt; m++) s = fmaf(as_[n][m], vs[m][d], s);
        ob[(size_t)n * Cn + d] = s;
    }
}

// ---------------- SGEMM 128x128x8, 8x8 per-thread register tile -----------------
// EPI 0: +bias            -> Cout row-major
// EPI 1: +bias +res, window-reverse+unshift scatter (proj)  -> Cout (BHWC)
// EPI 2: +bias, exact GELU -> Cout
// EPI 3: +bias +res        -> Cout
template<int EPI>
__global__ __launch_bounds__(256, 2) void sgemm_k(
    const float* __restrict__ A, const float* __restrict__ Bw,
    const float* __restrict__ bias, const float* __restrict__ res,
    float* __restrict__ Cout, int N, int K)
{
    __shared__ float As[8][128];
    __shared__ float Bs[8][128];
    const int t = threadIdx.x;
    const int mBase = blockIdx.x * 128;
    const int nBase = blockIdx.y * 128;
    const int arow = t >> 1;
    const int acol = (t & 1) * 4;
    const int brow = t >> 5;
    const int bcol = (t & 31) * 4;
    const float* Ag = A  + (size_t)(mBase + arow) * K + acol;
    const float* Bg = Bw + (size_t)brow * N + nBase + bcol;
    const int trow = (t >> 4) * 8;
    const int tcol = (t & 15) * 8;
    float acc[8][8] = {};

    for (int k0 = 0; k0 < K; k0 += 8) {
        float4 av = *(const float4*)Ag;
        float4 bv = *(const float4*)Bg;
        As[acol + 0][arow] = av.x;
        As[acol + 1][arow] = av.y;
        As[acol + 2][arow] = av.z;
        As[acol + 3][arow] = av.w;
        *(float4*)&Bs[brow][bcol] = bv;
        __syncthreads();
        #pragma unroll
        for (int kk = 0; kk < 8; kk++) {
            float ar[8], br[8];
            *(float4*)(ar)     = *(const float4*)&As[kk][trow];
            *(float4*)(ar + 4) = *(const float4*)&As[kk][trow + 4];
            *(float4*)(br)     = *(const float4*)&Bs[kk][tcol];
            *(float4*)(br + 4) = *(const float4*)&Bs[kk][tcol + 4];
            #pragma unroll
            for (int i = 0; i < 8; i++)
                #pragma unroll
                for (int j = 0; j < 8; j++)
                    acc[i][j] = fmaf(ar[i], br[j], acc[i][j]);
        }
        __syncthreads();
        Ag += 8;
        Bg += (size_t)8 * N;
    }

    #pragma unroll
    for (int i = 0; i < 8; i++) {
        int r = mBase + trow + i;
        size_t orow = 0;
        if (EPI == 1) {
            int b = r / Sn, rem = r % Sn;
            int wl = rem / Nt, n = rem % Nt;
            int wh = wl >> 3, ww = wl & 7;
            int ii = n / 7, jj = n % 7;
            int h = wh * 7 + ii + SSn; if (h >= Hn) h -= Hn;
            int w = ww * 7 + jj + SSn; if (w >= Wn) w -= Wn;
            orow = (size_t)b * Sn + h * Wn + w;
        }
        #pragma unroll
        for (int j = 0; j < 8; j++) {
            int col = nBase + tcol + j;
            float v = acc[i][j] + bias[col];
            if (EPI == 0) {
                Cout[(size_t)r * N + col] = v;
            } else if (EPI == 1) {
                Cout[orow * (size_t)N + col] = v + res[orow * (size_t)N + col];
            } else if (EPI == 2) {
                Cout[(size_t)r * N + col] = 0.5f * v * (1.0f + erff(v * 0.70710678118654752f));
            } else {
                Cout[(size_t)r * N + col] = v + res[(size_t)r * N + col];
            }
        }
    }
}

// ---------------- launch ----------------
extern "C" void kernel_launch(void* const* d_in, const int* in_sizes, int n_in,
                              void* d_out, int out_size)
{
    const float* x       = (const float*)d_in[0];
    const float* qkv_w   = (const float*)d_in[1];
    const float* qkv_b   = (const float*)d_in[2];
    const float* proj_w  = (const float*)d_in[3];
    const float* proj_b  = (const float*)d_in[4];
    const float* rpb     = (const float*)d_in[5];
    const float* n1w     = (const float*)d_in[6];
    const float* n1b     = (const float*)d_in[7];
    const float* n2w     = (const float*)d_in[8];
    const float* n2b     = (const float*)d_in[9];
    const float* fc1_w   = (const float*)d_in[10];
    const float* fc1_b   = (const float*)d_in[11];
    const float* fc2_w   = (const float*)d_in[12];
    const float* fc2_b   = (const float*)d_in[13];
    float* out = (float*)d_out;

    float *xp, *xw, *qkv, *ao, *y, *xn, *hid;
    cudaGetSymbolAddress((void**)&xp,  g_xp);
    cudaGetSymbolAddress((void**)&xw,  g_xw);
    cudaGetSymbolAddress((void**)&qkv, g_qkv);
    cudaGetSymbolAddress((void**)&ao,  g_ao);
    cudaGetSymbolAddress((void**)&y,   g_y);
    cudaGetSymbolAddress((void**)&xn,  g_xn);
    cudaGetSymbolAddress((void**)&hid, g_hid);

    dim3 tb(32, 8);
    // 1. BCHW -> BHWC
    transpose_k<<<dim3(Sn / 32, Cn / 32, Bn), tb>>>(x, xp, Cn, Sn);
    // 2. shift + window partition + LN1
    ln_kernel<true><<<Mrows, 128>>>(xp, n1w, n1b, xw);
    // 3. QKV GEMM (100352 x 1152 x 384)
    sgemm_k<0><<<dim3(Mrows / 128, (3 * Cn) / 128), 256>>>(xw, qkv_w, qkv_b, nullptr, qkv, 3 * Cn, Cn);
    // 4. windowed attention (fused bias/mask/softmax/@V)
    attn_kernel<<<Bn * 64 * NHn, 128>>>(qkv, rpb, ao);
    // 5. proj GEMM + window-reverse + unshift + residual  (-> y, BHWC)
    sgemm_k<1><<<dim3(Mrows / 128, Cn / 128), 256>>>(ao, proj_w, proj_b, xp, y, Cn, Cn);
    // 6. LN2
    ln_kernel<false><<<Mrows, 128>>>(y, n2w, n2b, xn);
    // 7. FC1 + GELU (100352 x 1536 x 384)
    sgemm_k<2><<<dim3(Mrows / 128, HIDn / 128), 256>>>(xn, fc1_w, fc1_b, nullptr, hid, HIDn, Cn);
    // 8. FC2 + residual (100352 x 384 x 1536) -> reuse ao as BHWC result
    sgemm_k<3><<<dim3(Mrows / 128, Cn / 128), 256>>>(hid, fc2_w, fc2_b, y, ao, Cn, HIDn);
    // 9. BHWC -> BCHW
    transpose_k<<<dim3(Cn / 32, Sn / 32, Bn), tb>>>(ao, out, Sn, Cn);
}

// round 4
// speedup vs baseline: 2.3692x; 2.3692x over previous
#include <cuda_runtime.h>
#include <math.h>

// ---------------- problem constants ----------------
#define Bn    32
#define Cn    384
#define Hn    56
#define Wn    56
#define WSn   7
#define SSn   3
#define NHn   12
#define Nt    49
#define HDn   32
#define Sn    (Hn*Wn)     // 3136
#define Mrows (Bn*Sn)     // 100352
#define HIDn  1536
#define SCALE 0.17677669529663688f

// ---------------- scratch ----------------
__device__ float g_xp [(size_t)Mrows*Cn];
__device__ float g_xw [(size_t)Mrows*Cn];
__device__ float g_qkv[(size_t)Mrows*3*Cn];
__device__ float g_ao [(size_t)Mrows*Cn];
__device__ float g_y  [(size_t)Mrows*Cn];
__device__ float g_xn [(size_t)Mrows*Cn];
__device__ float g_hid[(size_t)Mrows*HIDn];

// ---------------- transpose ----------------
__global__ void transpose_k(const float* __restrict__ in, float* __restrict__ out,
                            int R, int Cc)
{
    __shared__ float tile[32][33];
    int b  = blockIdx.z;
    int c0 = blockIdx.x * 32;
    int r0 = blockIdx.y * 32;
    const float* ib = in  + (size_t)b * R * Cc;
    float*       ob = out + (size_t)b * R * Cc;
    #pragma unroll
    for (int dy = threadIdx.y; dy < 32; dy += 8)
        tile[dy][threadIdx.x] = ib[(size_t)(r0 + dy) * Cc + c0 + threadIdx.x];
    __syncthreads();
    #pragma unroll
    for (int dy = threadIdx.y; dy < 32; dy += 8)
        ob[(size_t)(c0 + dy) * R + r0 + threadIdx.x] = tile[threadIdx.x][dy];
}

// ---------------- LayerNorm (optional shift+window gather) ----------------
template<bool GATHER>
__global__ void ln_kernel(const float* __restrict__ in, const float* __restrict__ gamma,
                          const float* __restrict__ beta, float* __restrict__ out)
{
    int tkn = blockIdx.x;
    const float* src;
    if (GATHER) {
        int wl = tkn / Nt, n = tkn % Nt;
        int b = wl >> 6, wi = wl & 63;
        int wh = wi >> 3, ww = wi & 7;
        int i = n / 7, j = n % 7;
        int h = wh * 7 + i + SSn; if (h >= Hn) h -= Hn;
        int w = ww * 7 + j + SSn; if (w >= Wn) w -= Wn;
        src = in + ((size_t)b * Sn + h * Wn + w) * Cn;
    } else {
        src = in + (size_t)tkn * Cn;
    }
    int t = threadIdx.x;
    float v0 = src[t], v1 = src[t + 128], v2 = src[t + 256];
    float s  = v0 + v1 + v2;
    float sq = v0 * v0 + v1 * v1 + v2 * v2;
    #pragma unroll
    for (int off = 16; off; off >>= 1) {
        s  += __shfl_xor_sync(0xffffffffu, s,  off);
        sq += __shfl_xor_sync(0xffffffffu, sq, off);
    }
    __shared__ float ws[4], wq[4];
    if ((t & 31) == 0) { ws[t >> 5] = s; wq[t >> 5] = sq; }
    __syncthreads();
    s  = ws[0] + ws[1] + ws[2] + ws[3];
    sq = wq[0] + wq[1] + wq[2] + wq[3];
    float mean = s * (1.0f / Cn);
    float var  = sq * (1.0f / Cn) - mean * mean;
    float rstd = rsqrtf(var + 1e-5f);
    float* dst = out + (size_t)tkn * Cn;
    dst[t]       = (v0 - mean) * rstd * gamma[t]       + beta[t];
    dst[t + 128] = (v1 - mean) * rstd * gamma[t + 128] + beta[t + 128];
    dst[t + 256] = (v2 - mean) * rstd * gamma[t + 256] + beta[t + 256];
}

// ---------------- fused windowed attention ----------------
__global__ void attn_kernel(const float* __restrict__ qkv,
                            const float* __restrict__ rpb,
                            float* __restrict__ out)
{
    int blk = blockIdx.x;
    int wl  = blk / NHn;
    int hh  = blk % NHn;
    int wi  = wl & 63;
    int wh  = wi >> 3, ww = wi & 7;

    __shared__ float qs[Nt][33], ks[Nt][33], vs[Nt][33];
    __shared__ float as_[Nt][50];

    int t = threadIdx.x;
    const float* base = qkv + (size_t)wl * Nt * (3 * Cn) + hh * HDn;
    for (int e = t; e < Nt * HDn; e += 128) {
        int n = e >> 5, d = e & 31;
        const float* row = base + (size_t)n * (3 * Cn);
        qs[n][d] = row[d] * SCALE;
        ks[n][d] = row[Cn + d];
        vs[n][d] = row[2 * Cn + d];
    }
    __syncthreads();

    for (int e = t; e < Nt * Nt; e += 128) {
        int n = e / Nt, m = e % Nt;
        float s = 0.0f;
        #pragma unroll
        for (int d = 0; d < HDn; d++) s = fmaf(qs[n][d], ks[m][d], s);
        int i1 = n / 7, j1 = n % 7, i2 = m / 7, j2 = m % 7;
        s += rpb[((i1 - i2 + 6) * 13 + (j1 - j2 + 6)) * NHn + hh];
        int h1 = wh * 7 + i1, w1 = ww * 7 + j1;
        int h2 = wh * 7 + i2, w2 = ww * 7 + j2;
        int r1 = (h1 < 49 ? 0 : (h1 < 53 ? 1 : 2)) * 3 + (w1 < 49 ? 0 : (w1 < 53 ? 1 : 2));
        int r2 = (h2 < 49 ? 0 : (h2 < 53 ? 1 : 2)) * 3 + (w2 < 49 ? 0 : (w2 < 53 ? 1 : 2));
        if (r1 != r2) s -= 100.0f;
        as_[n][m] = s;
    }
    __syncthreads();

    if (t < Nt) {
        float mx = -1e30f;
        #pragma unroll
        for (int m = 0; m < Nt; m++) mx = fmaxf(mx, as_[t][m]);
        float sm = 0.0f;
        #pragma unroll
        for (int m = 0; m < Nt; m++) { float e2 = expf(as_[t][m] - mx); as_[t][m] = e2; sm += e2; }
        float inv = 1.0f / sm;
        #pragma unroll
        for (int m = 0; m < Nt; m++) as_[t][m] *= inv;
    }
    __syncthreads();

    float* ob = out + (size_t)wl * Nt * Cn + hh * HDn;
    for (int e = t; e < Nt * HDn; e += 128) {
        int n = e >> 5, d = e & 31;
        float s = 0.0f;
        #pragma unroll
        for (int m = 0; m < Nt; m++) s = fmaf(as_[n][m], vs[m][d], s);
        ob[(size_t)n * Cn + d] = s;
    }
}

// ---------------- TF32 tensor-core GEMM 128x128x16, mma.m16n8k8 ----------------
__device__ __forceinline__ unsigned f2tf(float f) {
    unsigned u;
    asm("cvt.rna.tf32.f32 %0, %1;" : "=r"(u) : "f"(f));
    return u;
}
__device__ __forceinline__ void mma_tf32(float* c, const unsigned* a, const unsigned* b) {
    asm volatile(
        "mma.sync.aligned.m16n8k8.row.col.f32.tf32.tf32.f32 "
        "{%0,%1,%2,%3}, {%4,%5,%6,%7}, {%8,%9}, {%0,%1,%2,%3};\n"
        : "+f"(c[0]), "+f"(c[1]), "+f"(c[2]), "+f"(c[3])
        : "r"(a[0]), "r"(a[1]), "r"(a[2]), "r"(a[3]), "r"(b[0]), "r"(b[1]));
}

// EPI 0: +bias               EPI 1: +bias +res, window-reverse scatter
// EPI 2: +bias, GELU         EPI 3: +bias +res
template<int EPI>
__global__ __launch_bounds__(256, 2) void tgemm_k(
    const float* __restrict__ A, const float* __restrict__ Bw,
    const float* __restrict__ bias, const float* __restrict__ res,
    float* __restrict__ Cout, int N, int K)
{
    // smem: [buf][k(16)][m/n(128)] stride 136 -> bank = (8k + mn) % 32, conflict-free
    __shared__ unsigned As[2][16][136];
    __shared__ unsigned Bs[2][16][136];

    const int t    = threadIdx.x;
    const int lane = t & 31;
    const int warp = t >> 5;
    const int g    = lane >> 2;      // groupID 0..7
    const int tg   = lane & 3;       // thread-in-group 0..3
    const int wM   = (warp & 1) * 64;  // warp tile 64x32
    const int wN   = (warp >> 1) * 32;

    const int mBase = blockIdx.x * 128;
    const int nBase = blockIdx.y * 128;

    // global load mapping
    const int aRow = t >> 2;          // 0..63  (+64 for second)
    const int aK   = (t & 3) * 4;
    const int bK   = t >> 5;          // 0..7   (+8 for second)
    const int bN   = (t & 31) * 4;

    const float* Ag = A  + (size_t)(mBase + aRow) * K + aK;
    const float* Bg = Bw + (size_t)bK * N + nBase + bN;
    const size_t aStep2 = (size_t)64 * K;
    const size_t bStep2 = (size_t)8 * N;

    float acc[4][4][4] = {};
    const int niter = K >> 4;

    // prologue: tile 0 -> smem buf 0
    {
        float4 a0 = *(const float4*)Ag;
        float4 a1 = *(const float4*)(Ag + aStep2);
        float4 b0 = *(const float4*)Bg;
        float4 b1 = *(const float4*)(Bg + bStep2);
        As[0][aK + 0][aRow]      = f2tf(a0.x);
        As[0][aK + 1][aRow]      = f2tf(a0.y);
        As[0][aK + 2][aRow]      = f2tf(a0.z);
        As[0][aK + 3][aRow]      = f2tf(a0.w);
        As[0][aK + 0][aRow + 64] = f2tf(a1.x);
        As[0][aK + 1][aRow + 64] = f2tf(a1.y);
        As[0][aK + 2][aRow + 64] = f2tf(a1.z);
        As[0][aK + 3][aRow + 64] = f2tf(a1.w);
        Bs[0][bK][bN + 0]     = f2tf(b0.x);
        Bs[0][bK][bN + 1]     = f2tf(b0.y);
        Bs[0][bK][bN + 2]     = f2tf(b0.z);
        Bs[0][bK][bN + 3]     = f2tf(b0.w);
        Bs[0][bK + 8][bN + 0] = f2tf(b1.x);
        Bs[0][bK + 8][bN + 1] = f2tf(b1.y);
        Bs[0][bK + 8][bN + 2] = f2tf(b1.z);
        Bs[0][bK + 8][bN + 3] = f2tf(b1.w);
        Ag += 16; Bg += (size_t)16 * N;
    }
    __syncthreads();

    int buf = 0;
    for (int i = 0; i < niter; i++) {
        float4 a0, a1, b0, b1;
        bool more = (i + 1 < niter);
        if (more) {
            a0 = *(const float4*)Ag;
            a1 = *(const float4*)(Ag + aStep2);
            b0 = *(const float4*)Bg;
            b1 = *(const float4*)(Bg + bStep2);
            Ag += 16; Bg += (size_t)16 * N;
        }

        // compute on buf
        #pragma unroll
        for (int kk = 0; kk < 2; kk++) {
            const int kb = kk * 8;
            unsigned af[4][4], bfr[4][2];
            #pragma unroll
            for (int mt = 0; mt < 4; mt++) {
                int m = wM + mt * 16 + g;
                af[mt][0] = As[buf][kb + tg][m];
                af[mt][1] = As[buf][kb + tg][m + 8];
                af[mt][2] = As[buf][kb + tg + 4][m];
                af[mt][3] = As[buf][kb + tg + 4][m + 8];
            }
            #pragma unroll
            for (int nt = 0; nt < 4; nt++) {
                int n = wN + nt * 8 + g;
                bfr[nt][0] = Bs[buf][kb + tg][n];
                bfr[nt][1] = Bs[buf][kb + tg + 4][n];
            }
            #pragma unroll
            for (int mt = 0; mt < 4; mt++)
                #pragma unroll
                for (int nt = 0; nt < 4; nt++)
                    mma_tf32(acc[mt][nt], af[mt], bfr[nt]);
        }

        if (more) {
            int nb = buf ^ 1;
            As[nb][aK + 0][aRow]      = f2tf(a0.x);
            As[nb][aK + 1][aRow]      = f2tf(a0.y);
            As[nb][aK + 2][aRow]      = f2tf(a0.z);
            As[nb][aK + 3][aRow]      = f2tf(a0.w);
            As[nb][aK + 0][aRow + 64] = f2tf(a1.x);
            As[nb][aK + 1][aRow + 64] = f2tf(a1.y);
            As[nb][aK + 2][aRow + 64] = f2tf(a1.z);
            As[nb][aK + 3][aRow + 64] = f2tf(a1.w);
            Bs[nb][bK][bN + 0]     = f2tf(b0.x);
            Bs[nb][bK][bN + 1]     = f2tf(b0.y);
            Bs[nb][bK][bN + 2]     = f2tf(b0.z);
            Bs[nb][bK][bN + 3]     = f2tf(b0.w);
            Bs[nb][bK + 8][bN + 0] = f2tf(b1.x);
            Bs[nb][bK + 8][bN + 1] = f2tf(b1.y);
            Bs[nb][bK + 8][bN + 2] = f2tf(b1.z);
            Bs[nb][bK + 8][bN + 3] = f2tf(b1.w);
        }
        __syncthreads();
        buf ^= 1;
    }

    // epilogue
    #pragma unroll
    for (int mt = 0; mt < 4; mt++) {
        #pragma unroll
        for (int half = 0; half < 2; half++) {
            int r = mBase + wM + mt * 16 + g + half * 8;
            size_t orow = (size_t)r;
            if (EPI == 1) {
                int b = r / Sn, rem = r % Sn;
                int wl = rem / Nt, n = rem % Nt;
                int wh = wl >> 3, ww = wl & 7;
                int ii = n / 7, jj = n % 7;
                int h = wh * 7 + ii + SSn; if (h >= Hn) h -= Hn;
                int w = ww * 7 + jj + SSn; if (w >= Wn) w -= Wn;
                orow = (size_t)b * Sn + h * Wn + w;
            }
            #pragma unroll
            for (int nt = 0; nt < 4; nt++) {
                int col = nBase + wN + nt * 8 + 2 * tg;
                float v0 = acc[mt][nt][half * 2 + 0] + bias[col];
                float v1 = acc[mt][nt][half * 2 + 1] + bias[col + 1];
                if (EPI == 0) {
                    float2 o = {v0, v1};
                    *(float2*)&Cout[(size_t)r * N + col] = o;
                } else if (EPI == 1) {
                    float2 rr = *(const float2*)&res[orow * N + col];
                    float2 o = {v0 + rr.x, v1 + rr.y};
                    *(float2*)&Cout[orow * N + col] = o;
                } else if (EPI == 2) {
                    float2 o;
                    o.x = 0.5f * v0 * (1.0f + erff(v0 * 0.70710678118654752f));
                    o.y = 0.5f * v1 * (1.0f + erff(v1 * 0.70710678118654752f));
                    *(float2*)&Cout[(size_t)r * N + col] = o;
                } else {
                    float2 rr = *(const float2*)&res[(size_t)r * N + col];
                    float2 o = {v0 + rr.x, v1 + rr.y};
                    *(float2*)&Cout[(size_t)r * N + col] = o;
                }
            }
        }
    }
}

// ---------------- launch ----------------
extern "C" void kernel_launch(void* const* d_in, const int* in_sizes, int n_in,
                              void* d_out, int out_size)
{
    const float* x       = (const float*)d_in[0];
    const float* qkv_w   = (const float*)d_in[1];
    const float* qkv_b   = (const float*)d_in[2];
    const float* proj_w  = (const float*)d_in[3];
    const float* proj_b  = (const float*)d_in[4];
    const float* rpb     = (const float*)d_in[5];
    const float* n1w     = (const float*)d_in[6];
    const float* n1b     = (const float*)d_in[7];
    const float* n2w     = (const float*)d_in[8];
    const float* n2b     = (const float*)d_in[9];
    const float* fc1_w   = (const float*)d_in[10];
    const float* fc1_b   = (const float*)d_in[11];
    const float* fc2_w   = (const float*)d_in[12];
    const float* fc2_b   = (const float*)d_in[13];
    float* out = (float*)d_out;

    float *xp, *xw, *qkv, *ao, *y, *xn, *hid;
    cudaGetSymbolAddress((void**)&xp,  g_xp);
    cudaGetSymbolAddress((void**)&xw,  g_xw);
    cudaGetSymbolAddress((void**)&qkv, g_qkv);
    cudaGetSymbolAddress((void**)&ao,  g_ao);
    cudaGetSymbolAddress((void**)&y,   g_y);
    cudaGetSymbolAddress((void**)&xn,  g_xn);
    cudaGetSymbolAddress((void**)&hid, g_hid);

    dim3 tb(32, 8);
    transpose_k<<<dim3(Sn / 32, Cn / 32, Bn), tb>>>(x, xp, Cn, Sn);
    ln_kernel<true><<<Mrows, 128>>>(xp, n1w, n1b, xw);
    tgemm_k<0><<<dim3(Mrows / 128, (3 * Cn) / 128), 256>>>(xw, qkv_w, qkv_b, nullptr, qkv, 3 * Cn, Cn);
    attn_kernel<<<Bn * 64 * NHn, 128>>>(qkv, rpb, ao);
    tgemm_k<1><<<dim3(Mrows / 128, Cn / 128), 256>>>(ao, proj_w, proj_b, xp, y, Cn, Cn);
    ln_kernel<false><<<Mrows, 128>>>(y, n2w, n2b, xn);
    tgemm_k<2><<<dim3(Mrows / 128, HIDn / 128), 256>>>(xn, fc1_w, fc1_b, nullptr, hid, HIDn, Cn);
    tgemm_k<3><<<dim3(Mrows / 128, Cn / 128), 256>>>(hid, fc2_w, fc2_b, y, ao, Cn, HIDn);
    transpose_k<<<dim3(Cn / 32, Sn / 32, Bn), tb>>>(ao, out, Sn, Cn);
}

// round 5
// speedup vs baseline: 2.6710x; 1.1274x over previous
#include <cuda_runtime.h>
#include <math.h>

// ---------------- problem constants ----------------
#define Bn    32
#define Cn    384
#define Hn    56
#define Wn    56
#define SSn   3
#define NHn   12
#define Nt    49
#define HDn   32
#define Sn    (Hn*Wn)     // 3136
#define Mrows (Bn*Sn)     // 100352
#define HIDn  1536
#define SCALE 0.17677669529663688f

// ---------------- scratch ----------------
__device__ float g_xp [(size_t)Mrows*Cn];
__device__ float g_xw [(size_t)Mrows*Cn];
__device__ float g_qkv[(size_t)Mrows*3*Cn];
__device__ float g_ao [(size_t)Mrows*Cn];
__device__ float g_y  [(size_t)Mrows*Cn];
__device__ float g_xn [(size_t)Mrows*Cn];
__device__ float g_hid[(size_t)Mrows*HIDn];
__device__ float g_wqkv[Cn*3*Cn];
__device__ float g_wproj[Cn*Cn];
__device__ float g_wfc1[Cn*HIDn];
__device__ float g_wfc2[HIDn*Cn];
__device__ float g_bm[4*NHn*Nt*Nt];

// ---------------- helpers ----------------
__device__ __forceinline__ float rtf(float f) {
    unsigned u;
    asm("cvt.rna.tf32.f32 %0, %1;" : "=r"(u) : "f"(f));
    return __uint_as_float(u);
}
__device__ __forceinline__ void mma_tf32(float* c, const unsigned* a, const unsigned* b) {
    asm volatile(
        "mma.sync.aligned.m16n8k8.row.col.f32.tf32.tf32.f32 "
        "{%0,%1,%2,%3}, {%4,%5,%6,%7}, {%8,%9}, {%0,%1,%2,%3};\n"
        : "+f"(c[0]), "+f"(c[1]), "+f"(c[2]), "+f"(c[3])
        : "r"(a[0]), "r"(a[1]), "r"(a[2]), "r"(a[3]), "r"(b[0]), "r"(b[1]));
}
__device__ __forceinline__ void cpa16(void* dst, const void* src) {
    unsigned s = (unsigned)__cvta_generic_to_shared(dst);
    asm volatile("cp.async.cg.shared.global [%0], [%1], 16;\n" :: "r"(s), "l"(src));
}
__device__ __forceinline__ void cpcommit() { asm volatile("cp.async.commit_group;\n"); }
template<int n> __device__ __forceinline__ void cpwait() { asm volatile("cp.async.wait_group %0;\n" :: "n"(n)); }

// ---------------- tiny preprocessors ----------------
__global__ void cvtw_k(const float* __restrict__ in, float* __restrict__ out, int n) {
    int i = blockIdx.x * 256 + threadIdx.x;
    if (i < n) out[i] = rtf(in[i]);
}

__global__ void bm_k(const float* __restrict__ rpb, float* __restrict__ bm) {
    int head = blockIdx.x % NHn;
    int type = blockIdx.x / NHn;            // th*2 + tw
    int wh = (type >> 1) ? 7 : 0;
    int ww = (type & 1)  ? 7 : 0;
    float* dst = bm + (size_t)blockIdx.x * (Nt * Nt);
    for (int e = threadIdx.x; e < Nt * Nt; e += 128) {
        int n = e / Nt, m = e - n * Nt;
        int i1 = n / 7, j1 = n % 7, i2 = m / 7, j2 = m % 7;
        float v = rpb[((i1 - i2 + 6) * 13 + (j1 - j2 + 6)) * NHn + head];
        int h1 = wh * 7 + i1, w1 = ww * 7 + j1;
        int h2 = wh * 7 + i2, w2 = ww * 7 + j2;
        int r1 = (h1 < 49 ? 0 : (h1 < 53 ? 1 : 2)) * 3 + (w1 < 49 ? 0 : (w1 < 53 ? 1 : 2));
        int r2 = (h2 < 49 ? 0 : (h2 < 53 ? 1 : 2)) * 3 + (w2 < 49 ? 0 : (w2 < 53 ? 1 : 2));
        if (r1 != r2) v -= 100.0f;
        dst[e] = v;
    }
}

// ---------------- transpose ----------------
__global__ void transpose_k(const float* __restrict__ in, float* __restrict__ out,
                            int R, int Cc)
{
    __shared__ float tile[32][33];
    int b  = blockIdx.z;
    int c0 = blockIdx.x * 32;
    int r0 = blockIdx.y * 32;
    const float* ib = in  + (size_t)b * R * Cc;
    float*       ob = out + (size_t)b * R * Cc;
    #pragma unroll
    for (int dy = threadIdx.y; dy < 32; dy += 8)
        tile[dy][threadIdx.x] = ib[(size_t)(r0 + dy) * Cc + c0 + threadIdx.x];
    __syncthreads();
    #pragma unroll
    for (int dy = threadIdx.y; dy < 32; dy += 8)
        ob[(size_t)(c0 + dy) * R + r0 + threadIdx.x] = tile[threadIdx.x][dy];
}

// ---------------- LayerNorm (tf32-rounded output) ----------------
template<bool GATHER>
__global__ void ln_kernel(const float* __restrict__ in, const float* __restrict__ gamma,
                          const float* __restrict__ beta, float* __restrict__ out)
{
    int tkn = blockIdx.x;
    const float* src;
    if (GATHER) {
        int wl = tkn / Nt, n = tkn % Nt;
        int b = wl >> 6, wi = wl & 63;
        int wh = wi >> 3, ww = wi & 7;
        int i = n / 7, j = n % 7;
        int h = wh * 7 + i + SSn; if (h >= Hn) h -= Hn;
        int w = ww * 7 + j + SSn; if (w >= Wn) w -= Wn;
        src = in + ((size_t)b * Sn + h * Wn + w) * Cn;
    } else {
        src = in + (size_t)tkn * Cn;
    }
    int t = threadIdx.x;
    float v0 = src[t], v1 = src[t + 128], v2 = src[t + 256];
    float s  = v0 + v1 + v2;
    float sq = v0 * v0 + v1 * v1 + v2 * v2;
    #pragma unroll
    for (int off = 16; off; off >>= 1) {
        s  += __shfl_xor_sync(0xffffffffu, s,  off);
        sq += __shfl_xor_sync(0xffffffffu, sq, off);
    }
    __shared__ float ws[4], wq[4];
    if ((t & 31) == 0) { ws[t >> 5] = s; wq[t >> 5] = sq; }
    __syncthreads();
    s  = ws[0] + ws[1] + ws[2] + ws[3];
    sq = wq[0] + wq[1] + wq[2] + wq[3];
    float mean = s * (1.0f / Cn);
    float var  = sq * (1.0f / Cn) - mean * mean;
    float rstd = rsqrtf(var + 1e-5f);
    float* dst = out + (size_t)tkn * Cn;
    dst[t]       = rtf((v0 - mean) * rstd * gamma[t]       + beta[t]);
    dst[t + 128] = rtf((v1 - mean) * rstd * gamma[t + 128] + beta[t + 128]);
    dst[t + 256] = rtf((v2 - mean) * rstd * gamma[t + 256] + beta[t + 256]);
}

// ---------------- fused windowed attention (BM table, tf32-rounded out) ------
__global__ void attn_kernel(const float* __restrict__ qkv,
                            const float* __restrict__ bm,
                            float* __restrict__ out)
{
    int blk = blockIdx.x;
    int wl  = blk / NHn;
    int hh  = blk % NHn;
    int wi  = wl & 63;
    int wh  = wi >> 3, ww = wi & 7;
    int type = ((wh == 7) ? 2 : 0) | ((ww == 7) ? 1 : 0);

    __shared__ float qs[Nt][33], ks[Nt][33], vs[Nt][33];
    __shared__ float as_[Nt][50];

    int t = threadIdx.x;
    const float* base = qkv + (size_t)wl * Nt * (3 * Cn) + hh * HDn;
    for (int e = t; e < Nt * 8; e += 128) {
        int n = e >> 3, d4 = (e & 7) * 4;
        const float* row = base + (size_t)n * (3 * Cn);
        float4 q4 = *(const float4*)(row + d4);
        float4 k4 = *(const float4*)(row + Cn + d4);
        float4 v4 = *(const float4*)(row + 2 * Cn + d4);
        qs[n][d4] = q4.x * SCALE; qs[n][d4+1] = q4.y * SCALE;
        qs[n][d4+2] = q4.z * SCALE; qs[n][d4+3] = q4.w * SCALE;
        ks[n][d4] = k4.x; ks[n][d4+1] = k4.y; ks[n][d4+2] = k4.z; ks[n][d4+3] = k4.w;
        vs[n][d4] = v4.x; vs[n][d4+1] = v4.y; vs[n][d4+2] = v4.z; vs[n][d4+3] = v4.w;
    }
    __syncthreads();

    const float* bmb = bm + (size_t)(type * NHn + hh) * (Nt * Nt);
    for (int e = t; e < Nt * Nt; e += 128) {
        int n = e / Nt, m = e - n * Nt;
        float s = bmb[e];
        #pragma unroll
        for (int d = 0; d < HDn; d++) s = fmaf(qs[n][d], ks[m][d], s);
        as_[n][m] = s;
    }
    __syncthreads();

    {   // warp-per-row softmax
        int wp = t >> 5, ln_ = t & 31;
        for (int r = wp; r < Nt; r += 4) {
            float a0 = as_[r][ln_];
            float a1 = (ln_ + 32 < Nt) ? as_[r][ln_ + 32] : -1e30f;
            float mx = fmaxf(a0, a1);
            #pragma unroll
            for (int off = 16; off; off >>= 1) mx = fmaxf(mx, __shfl_xor_sync(0xffffffffu, mx, off));
            float e0 = __expf(a0 - mx);
            float e1 = (ln_ + 32 < Nt) ? __expf(a1 - mx) : 0.0f;
            float sm_ = e0 + e1;
            #pragma unroll
            for (int off = 16; off; off >>= 1) sm_ += __shfl_xor_sync(0xffffffffu, sm_, off);
            float inv = 1.0f / sm_;
            as_[r][ln_] = e0 * inv;
            if (ln_ + 32 < Nt) as_[r][ln_ + 32] = e1 * inv;
        }
    }
    __syncthreads();

    float* ob = out + (size_t)wl * Nt * Cn + hh * HDn;
    for (int e = t; e < Nt * HDn; e += 128) {
        int n = e >> 5, d = e & 31;
        float s = 0.0f;
        #pragma unroll
        for (int m = 0; m < Nt; m++) s = fmaf(as_[n][m], vs[m][d], s);
        ob[(size_t)n * Cn + d] = rtf(s);
    }
}

// ---------------- TF32 GEMM 128x128x32, cp.async 3-stage -----------------
#define KT 32
#define STG 3
#define AS_STRIDE 36
#define BS_STRIDE 132
#define A_STG (128*AS_STRIDE)
#define B_STG (32*BS_STRIDE)
#define STG_SZ (A_STG + B_STG)
#define SMEM_BYTES (STG * STG_SZ * 4)

// EPI 0: +bias   1: +bias +res window-reverse scatter   2: +bias GELU(->tf32)   3: +bias +res
template<int EPI>
__global__ __launch_bounds__(256, 2) void tgemm_k(
    const float* __restrict__ A, const float* __restrict__ Bw,
    const float* __restrict__ bias, const float* __restrict__ res,
    float* __restrict__ Cout, int N, int K)
{
    extern __shared__ float sm[];
    const int t    = threadIdx.x;
    const int lane = t & 31;
    const int warp = t >> 5;
    const int g    = lane >> 2;
    const int tg   = lane & 3;
    const int wM   = (warp & 1) * 64;
    const int wN   = (warp >> 1) * 32;
    const int mBase = blockIdx.x * 128;
    const int nBase = blockIdx.y * 128;

    const int aRow = t >> 3;          // 0..31
    const int aKc  = (t & 7) * 4;     // 0..28
    const int bKr  = t >> 5;          // 0..7
    const int bNc  = (t & 31) * 4;

    const float* Agb = A + (size_t)mBase * K;
    const int niter = K / KT;

    // stage issue
    auto issue = [&](int stage, int k0) {
        float* As = sm + stage * STG_SZ;
        float* Bs = As + A_STG;
        #pragma unroll
        for (int i = 0; i < 4; i++) {
            int row = aRow + i * 32;
            cpa16(&As[row * AS_STRIDE + aKc], Agb + (size_t)row * K + k0 + aKc);
        }
        #pragma unroll
        for (int i = 0; i < 4; i++) {
            int kr = bKr + i * 8;
            cpa16(&Bs[kr * BS_STRIDE + bNc], Bw + (size_t)(k0 + kr) * N + nBase + bNc);
        }
        cpcommit();
    };

    issue(0, 0);
    issue(1, KT);

    float acc[4][4][4] = {};

    for (int kb = 0; kb < niter; kb++) {
        cpwait<1>();
        __syncthreads();
        if (kb + 2 < niter) issue((kb + 2) % STG, (kb + 2) * KT);

        const float* As = sm + (kb % STG) * STG_SZ;
        const float* Bs = As + A_STG;
        #pragma unroll
        for (int sk = 0; sk < 4; sk++) {
            const int kb8 = sk * 8;
            unsigned af[4][4], bfr[4][2];
            #pragma unroll
            for (int mt = 0; mt < 4; mt++) {
                int m = wM + mt * 16 + g;
                af[mt][0] = __float_as_uint(As[(size_t)m * AS_STRIDE + kb8 + tg]);
                af[mt][1] = __float_as_uint(As[(size_t)(m + 8) * AS_STRIDE + kb8 + tg]);
                af[mt][2] = __float_as_uint(As[(size_t)m * AS_STRIDE + kb8 + tg + 4]);
                af[mt][3] = __float_as_uint(As[(size_t)(m + 8) * AS_STRIDE + kb8 + tg + 4]);
            }
            #pragma unroll
            for (int nt = 0; nt < 4; nt++) {
                int n = wN + nt * 8 + g;
                bfr[nt][0] = __float_as_uint(Bs[(size_t)(kb8 + tg) * BS_STRIDE + n]);
                bfr[nt][1] = __float_as_uint(Bs[(size_t)(kb8 + tg + 4) * BS_STRIDE + n]);
            }
            #pragma unroll
            for (int mt = 0; mt < 4; mt++)
                #pragma unroll
                for (int nt = 0; nt < 4; nt++)
                    mma_tf32(acc[mt][nt], af[mt], bfr[nt]);
        }
        __syncthreads();
    }

    // epilogue
    #pragma unroll
    for (int mt = 0; mt < 4; mt++) {
        #pragma unroll
        for (int half = 0; half < 2; half++) {
            int r = mBase + wM + mt * 16 + g + half * 8;
            size_t orow = (size_t)r;
            if (EPI == 1) {
                int b = r / Sn, rem = r % Sn;
                int wl = rem / Nt, n = rem % Nt;
                int wh = wl >> 3, ww = wl & 7;
                int ii = n / 7, jj = n % 7;
                int h = wh * 7 + ii + SSn; if (h >= Hn) h -= Hn;
                int w = ww * 7 + jj + SSn; if (w >= Wn) w -= Wn;
                orow = (size_t)b * Sn + h * Wn + w;
            }
            #pragma unroll
            for (int nt = 0; nt < 4; nt++) {
                int col = nBase + wN + nt * 8 + 2 * tg;
                float v0 = acc[mt][nt][half * 2 + 0] + bias[col];
                float v1 = acc[mt][nt][half * 2 + 1] + bias[col + 1];
                if (EPI == 0) {
                    float2 o = {v0, v1};
                    *(float2*)&Cout[(size_t)r * N + col] = o;
                } else if (EPI == 1) {
                    float2 rr = *(const float2*)&res[orow * N + col];
                    float2 o = {v0 + rr.x, v1 + rr.y};
                    *(float2*)&Cout[orow * N + col] = o;
                } else if (EPI == 2) {
                    float2 o;
                    o.x = rtf(0.5f * v0 * (1.0f + erff(v0 * 0.70710678118654752f)));
                    o.y = rtf(0.5f * v1 * (1.0f + erff(v1 * 0.70710678118654752f)));
                    *(float2*)&Cout[(size_t)r * N + col] = o;
                } else {
                    float2 rr = *(const float2*)&res[(size_t)r * N + col];
                    float2 o = {v0 + rr.x, v1 + rr.y};
                    *(float2*)&Cout[(size_t)r * N + col] = o;
                }
            }
        }
    }
}

// ---------------- launch ----------------
extern "C" void kernel_launch(void* const* d_in, const int* in_sizes, int n_in,
                              void* d_out, int out_size)
{
    const float* x       = (const float*)d_in[0];
    const float* qkv_w   = (const float*)d_in[1];
    const float* qkv_b   = (const float*)d_in[2];
    const float* proj_w  = (const float*)d_in[3];
    const float* proj_b  = (const float*)d_in[4];
    const float* rpb     = (const float*)d_in[5];
    const float* n1w     = (const float*)d_in[6];
    const float* n1b     = (const float*)d_in[7];
    const float* n2w     = (const float*)d_in[8];
    const float* n2b     = (const float*)d_in[9];
    const float* fc1_w   = (const float*)d_in[10];
    const float* fc1_b   = (const float*)d_in[11];
    const float* fc2_w   = (const float*)d_in[12];
    const float* fc2_b   = (const float*)d_in[13];
    float* out = (float*)d_out;

    float *xp, *xw, *qkv, *ao, *y, *xn, *hid;
    float *wqkv, *wproj, *wfc1, *wfc2, *bm;
    cudaGetSymbolAddress((void**)&xp,  g_xp);
    cudaGetSymbolAddress((void**)&xw,  g_xw);
    cudaGetSymbolAddress((void**)&qkv, g_qkv);
    cudaGetSymbolAddress((void**)&ao,  g_ao);
    cudaGetSymbolAddress((void**)&y,   g_y);
    cudaGetSymbolAddress((void**)&xn,  g_xn);
    cudaGetSymbolAddress((void**)&hid, g_hid);
    cudaGetSymbolAddress((void**)&wqkv,  g_wqkv);
    cudaGetSymbolAddress((void**)&wproj, g_wproj);
    cudaGetSymbolAddress((void**)&wfc1,  g_wfc1);
    cudaGetSymbolAddress((void**)&wfc2,  g_wfc2);
    cudaGetSymbolAddress((void**)&bm,    g_bm);

    static bool attr_set = false;
    if (!attr_set) {
        cudaFuncSetAttribute(tgemm_k<0>, cudaFuncAttributeMaxDynamicSharedMemorySize, SMEM_BYTES);
        cudaFuncSetAttribute(tgemm_k<1>, cudaFuncAttributeMaxDynamicSharedMemorySize, SMEM_BYTES);
        cudaFuncSetAttribute(tgemm_k<2>, cudaFuncAttributeMaxDynamicSharedMemorySize, SMEM_BYTES);
        cudaFuncSetAttribute(tgemm_k<3>, cudaFuncAttributeMaxDynamicSharedMemorySize, SMEM_BYTES);
        attr_set = true;
    }

    // preprocess: weights -> tf32, bias+mask table
    cvtw_k<<<(Cn*3*Cn + 255)/256, 256>>>(qkv_w, wqkv, Cn*3*Cn);
    cvtw_k<<<(Cn*Cn   + 255)/256, 256>>>(proj_w, wproj, Cn*Cn);
    cvtw_k<<<(Cn*HIDn + 255)/256, 256>>>(fc1_w, wfc1, Cn*HIDn);
    cvtw_k<<<(HIDn*Cn + 255)/256, 256>>>(fc2_w, wfc2, HIDn*Cn);
    bm_k<<<4*NHn, 128>>>(rpb, bm);

    dim3 tb(32, 8);
    transpose_k<<<dim3(Sn / 32, Cn / 32, Bn), tb>>>(x, xp, Cn, Sn);
    ln_kernel<true><<<Mrows, 128>>>(xp, n1w, n1b, xw);
    tgemm_k<0><<<dim3(Mrows / 128, (3 * Cn) / 128), 256, SMEM_BYTES>>>(xw, wqkv, qkv_b, nullptr, qkv, 3 * Cn, Cn);
    attn_kernel<<<Bn * 64 * NHn, 128>>>(qkv, bm, ao);
    tgemm_k<1><<<dim3(Mrows / 128, Cn / 128), 256, SMEM_BYTES>>>(ao, wproj, proj_b, xp, y, Cn, Cn);
    ln_kernel<false><<<Mrows, 128>>>(y, n2w, n2b, xn);
    tgemm_k<2><<<dim3(Mrows / 128, HIDn / 128), 256, SMEM_BYTES>>>(xn, wfc1, fc1_b, nullptr, hid, HIDn, Cn);
    tgemm_k<3><<<dim3(Mrows / 128, Cn / 128), 256, SMEM_BYTES>>>(hid, wfc2, fc2_b, y, ao, Cn, HIDn);
    transpose_k<<<dim3(Cn / 32, Sn / 32, Bn), tb>>>(ao, out, Sn, Cn);
}